// round 11
// baseline (speedup 1.0000x reference)
#include <cuda_runtime.h>
#include <stdint.h>

#define ALG   248
#define PAD   33            // smem row stride (32 batches + 1 pad word)
#define TB    32            // batches per CTA
#define NWARP 8
#define KPW   31            // 248 / 8 k-values per warp
#define MAXNNZ 65536

// ---------------- device scratch (no allocations allowed) ----------------
__device__ __align__(16) uint2 g_sorted[MAXNNZ + 8];  // {pi | pj<<16, coeff*alpha}
__device__ int g_hist[ALG];
__device__ int g_cursor[ALG];
__device__ int g_seg[ALG + 1];

// ---------------- sort-by-k pipeline ----------------
__global__ void hist_kernel(const int* __restrict__ idx_k, int nnz) {
    int t = blockIdx.x * blockDim.x + threadIdx.x;
    if (t < nnz) atomicAdd(&g_hist[idx_k[t]], 1);
}

__global__ void scan_kernel() {
    if (threadIdx.x == 0) {
        int s = 0;
        for (int k = 0; k < ALG; ++k) {
            g_seg[k]    = s;
            g_cursor[k] = s;
            s += g_hist[k];
        }
        g_seg[ALG] = s;
    }
}

__global__ void scatter_kernel(const int* __restrict__ idx_i,
                               const int* __restrict__ idx_j,
                               const int* __restrict__ idx_k,
                               const float* __restrict__ coeff,
                               const float* __restrict__ alpha,
                               int nnz) {
    int t = blockIdx.x * blockDim.x + threadIdx.x;
    if (t >= nnz) return;
    int k   = idx_k[t];
    int pos = atomicAdd(&g_cursor[k], 1);
    unsigned pi = (unsigned)(idx_i[t] * PAD);       // pre-scaled smem row offset
    unsigned pj = (unsigned)(idx_j[t] * PAD);
    g_sorted[pos] = make_uint2(pi | (pj << 16), __float_as_uint(coeff[t] * alpha[0]));
}

// ---------------- main bilinear kernel ----------------
extern __shared__ float smem[];

__global__ __launch_bounds__(256, 2)
void bracket_kernel(const float* __restrict__ x, const float* __restrict__ y,
                    float* __restrict__ out, int batch) {
    float* xs = smem;                       // [ALG][PAD]
    float* ys = xs + ALG * PAD;             // [ALG][PAD]
    float* os = ys + ALG * PAD;             // [ALG][PAD]
    __shared__ int segs[ALG + 1];

    const int tid  = threadIdx.x;
    const int warp = tid >> 5;
    const int lane = tid & 31;
    const int b0   = blockIdx.x * TB;

    for (int k = tid; k <= ALG; k += blockDim.x) segs[k] = g_seg[k];

    // Stage x,y tile transposed: coalesced global reads, conflict-free smem writes.
    for (int b = warp; b < TB; b += NWARP) {
        const int gb = b0 + b;
        const bool ok = gb < batch;
        const float* xr = x + (size_t)gb * ALG;
        const float* yr = y + (size_t)gb * ALG;
        for (int d = lane; d < ALG; d += 32) {
            xs[d * PAD + b] = ok ? xr[d] : 0.f;
            ys[d * PAD + b] = ok ? yr[d] : 0.f;
        }
    }
    __syncthreads();

    // Each warp owns 31 k-values exclusively -> register accumulation, no atomics.
    const float* xl = xs + lane;            // lane == batch-within-tile
    const float* yl = ys + lane;
    const int k0 = warp * KPW;

    for (int k = k0; k < k0 + KPW; ++k) {
        int t = segs[k];
        const int e = segs[k + 1];
        float acc0 = 0.f, acc1 = 0.f;

        if ((t & 1) && t < e) {             // align to 16B for uint4 loads
            uint2 q = __ldg(&g_sorted[t]);
            acc0 = fmaf(__uint_as_float(q.y) * xl[q.x & 0xFFFFu], yl[q.x >> 16], acc0);
            ++t;
        }
        for (; t + 2 <= e; t += 2) {        // 2 triples per LDG.128
            uint4 q = __ldg((const uint4*)(g_sorted + t));
            acc0 = fmaf(__uint_as_float(q.y) * xl[q.x & 0xFFFFu], yl[q.x >> 16], acc0);
            acc1 = fmaf(__uint_as_float(q.w) * xl[q.z & 0xFFFFu], yl[q.z >> 16], acc1);
        }
        if (t < e) {
            uint2 q = __ldg(&g_sorted[t]);
            acc0 = fmaf(__uint_as_float(q.y) * xl[q.x & 0xFFFFu], yl[q.x >> 16], acc0);
        }
        os[k * PAD + lane] = acc0 + acc1;
    }
    __syncthreads();

    // Coalesced write-out (alpha already folded into coeff).
    for (int b = warp; b < TB; b += NWARP) {
        const int gb = b0 + b;
        if (gb >= batch) continue;
        float* orow = out + (size_t)gb * ALG;
        for (int d = lane; d < ALG; d += 32) orow[d] = os[d * PAD + b];
    }
}

// ---------------- launch ----------------
extern "C" void kernel_launch(void* const* d_in, const int* in_sizes, int n_in,
                              void* d_out, int out_size) {
    const float* x     = (const float*)d_in[0];
    const float* y     = (const float*)d_in[1];
    const int*   idx_i = (const int*)  d_in[2];
    const int*   idx_j = (const int*)  d_in[3];
    const int*   idx_k = (const int*)  d_in[4];
    const float* coeff = (const float*)d_in[5];
    const float* alpha = (const float*)d_in[6];

    int nnz = in_sizes[5];
    if (nnz > MAXNNZ) nnz = MAXNNZ;
    const int batch = in_sizes[0] / ALG;

    void* hist_ptr = nullptr;
    cudaGetSymbolAddress(&hist_ptr, g_hist);
    cudaMemsetAsync(hist_ptr, 0, ALG * sizeof(int));

    const int nb = (nnz + 255) / 256;
    hist_kernel   <<<nb, 256>>>(idx_k, nnz);
    scan_kernel   <<<1, 32>>>();
    scatter_kernel<<<nb, 256>>>(idx_i, idx_j, idx_k, coeff, alpha, nnz);

    const int smem_bytes = 3 * ALG * PAD * (int)sizeof(float);   // 98208 B
    cudaFuncSetAttribute(bracket_kernel,
                         cudaFuncAttributeMaxDynamicSharedMemorySize, smem_bytes);

    const int grid = (batch + TB - 1) / TB;                      // 256 CTAs
    bracket_kernel<<<grid, 256, smem_bytes>>>(x, y, (float*)d_out, batch);
}

// round 12
// speedup vs baseline: 1.0014x; 1.0014x over previous
#include <cuda_runtime.h>
#include <stdint.h>

#define ALG   248
#define PAD   33            // smem row stride (32 batches + 1 pad word)
#define TB    32            // batches per CTA
#define NWARP 8
#define KPW   31            // 248 / 8 k-values per warp
#define MAXNNZ 65536

// ---------------- device scratch (no allocations allowed) ----------------
__device__ __align__(16) uint2 g_sorted[MAXNNZ + 8];  // {pi | pj<<16, coeff*alpha}
__device__ int g_hist[ALG];
__device__ int g_cursor[ALG];
__device__ int g_seg[ALG + 1];

// ---------------- sort-by-k pipeline ----------------
__global__ void hist_kernel(const int* __restrict__ idx_k, int nnz) {
    int t = blockIdx.x * blockDim.x + threadIdx.x;
    if (t < nnz) atomicAdd(&g_hist[idx_k[t]], 1);
}

__global__ void scan_kernel() {
    if (threadIdx.x == 0) {
        int s = 0;
        for (int k = 0; k < ALG; ++k) {
            g_seg[k]    = s;
            g_cursor[k] = s;
            s += g_hist[k];
        }
        g_seg[ALG] = s;
    }
}

__global__ void scatter_kernel(const int* __restrict__ idx_i,
                               const int* __restrict__ idx_j,
                               const int* __restrict__ idx_k,
                               const float* __restrict__ coeff,
                               const float* __restrict__ alpha,
                               int nnz) {
    int t = blockIdx.x * blockDim.x + threadIdx.x;
    if (t >= nnz) return;
    int k   = idx_k[t];
    int pos = atomicAdd(&g_cursor[k], 1);
    unsigned pi = (unsigned)(idx_i[t] * PAD);       // pre-scaled smem row offset
    unsigned pj = (unsigned)(idx_j[t] * PAD);
    g_sorted[pos] = make_uint2(pi | (pj << 16), __float_as_uint(coeff[t] * alpha[0]));
}

// ---------------- main bilinear kernel ----------------
extern __shared__ float smem[];

__global__ __launch_bounds__(256, 2)
void bracket_kernel(const float* __restrict__ x, const float* __restrict__ y,
                    float* __restrict__ out, int batch) {
    float* xs = smem;                       // [ALG][PAD]
    float* ys = xs + ALG * PAD;             // [ALG][PAD]
    float* os = ys + ALG * PAD;             // [ALG][PAD]
    __shared__ int segs[ALG + 1];

    const int tid  = threadIdx.x;
    const int warp = tid >> 5;
    const int lane = tid & 31;
    const int b0   = blockIdx.x * TB;

    for (int k = tid; k <= ALG; k += blockDim.x) segs[k] = g_seg[k];

    // Stage x,y tile transposed: coalesced global reads, conflict-free smem writes.
    for (int b = warp; b < TB; b += NWARP) {
        const int gb = b0 + b;
        const bool ok = gb < batch;
        const float* xr = x + (size_t)gb * ALG;
        const float* yr = y + (size_t)gb * ALG;
        for (int d = lane; d < ALG; d += 32) {
            xs[d * PAD + b] = ok ? xr[d] : 0.f;
            ys[d * PAD + b] = ok ? yr[d] : 0.f;
        }
    }
    __syncthreads();

    // Each warp owns 31 k-values exclusively -> register accumulation, no atomics.
    const float* xl = xs + lane;            // lane == batch-within-tile
    const float* yl = ys + lane;
    const int k0 = warp * KPW;

    for (int k = k0; k < k0 + KPW; ++k) {
        int t = segs[k];
        const int e = segs[k + 1];
        float acc0 = 0.f, acc1 = 0.f;

        if ((t & 1) && t < e) {             // align to 16B for uint4 loads
            uint2 q = __ldg(&g_sorted[t]);
            acc0 = fmaf(__uint_as_float(q.y) * xl[q.x & 0xFFFFu], yl[q.x >> 16], acc0);
            ++t;
        }
        for (; t + 2 <= e; t += 2) {        // 2 triples per LDG.128
            uint4 q = __ldg((const uint4*)(g_sorted + t));
            acc0 = fmaf(__uint_as_float(q.y) * xl[q.x & 0xFFFFu], yl[q.x >> 16], acc0);
            acc1 = fmaf(__uint_as_float(q.w) * xl[q.z & 0xFFFFu], yl[q.z >> 16], acc1);
        }
        if (t < e) {
            uint2 q = __ldg(&g_sorted[t]);
            acc0 = fmaf(__uint_as_float(q.y) * xl[q.x & 0xFFFFu], yl[q.x >> 16], acc0);
        }
        os[k * PAD + lane] = acc0 + acc1;
    }
    __syncthreads();

    // Coalesced write-out (alpha already folded into coeff).
    for (int b = warp; b < TB; b += NWARP) {
        const int gb = b0 + b;
        if (gb >= batch) continue;
        float* orow = out + (size_t)gb * ALG;
        for (int d = lane; d < ALG; d += 32) orow[d] = os[d * PAD + b];
    }
}

// ---------------- launch ----------------
extern "C" void kernel_launch(void* const* d_in, const int* in_sizes, int n_in,
                              void* d_out, int out_size) {
    const float* x     = (const float*)d_in[0];
    const float* y     = (const float*)d_in[1];
    const int*   idx_i = (const int*)  d_in[2];
    const int*   idx_j = (const int*)  d_in[3];
    const int*   idx_k = (const int*)  d_in[4];
    const float* coeff = (const float*)d_in[5];
    const float* alpha = (const float*)d_in[6];

    int nnz = in_sizes[5];
    if (nnz > MAXNNZ) nnz = MAXNNZ;
    const int batch = in_sizes[0] / ALG;

    void* hist_ptr = nullptr;
    cudaGetSymbolAddress(&hist_ptr, g_hist);
    cudaMemsetAsync(hist_ptr, 0, ALG * sizeof(int));

    const int nb = (nnz + 255) / 256;
    hist_kernel   <<<nb, 256>>>(idx_k, nnz);
    scan_kernel   <<<1, 32>>>();
    scatter_kernel<<<nb, 256>>>(idx_i, idx_j, idx_k, coeff, alpha, nnz);

    const int smem_bytes = 3 * ALG * PAD * (int)sizeof(float);   // 98208 B
    cudaFuncSetAttribute(bracket_kernel,
                         cudaFuncAttributeMaxDynamicSharedMemorySize, smem_bytes);

    const int grid = (batch + TB - 1) / TB;                      // 256 CTAs
    bracket_kernel<<<grid, 256, smem_bytes>>>(x, y, (float*)d_out, batch);
}

// round 13
// speedup vs baseline: 1.0099x; 1.0084x over previous
#include <cuda_runtime.h>
#include <stdint.h>

#define ALG   248
#define PAD   33            // smem row stride (32 batches + 1 pad word)
#define TB    32            // batches per CTA
#define NWARP 8
#define KPW   31            // 248 / 8 k-values per warp
#define MAXNNZ 65536

// ---------------- device scratch (no allocations allowed) ----------------
__device__ __align__(16) uint2 g_sorted[MAXNNZ + 8];  // {pi | pj<<16, coeff*alpha}
__device__ int g_hist[ALG];
__device__ int g_cursor[ALG];
__device__ int g_seg[ALG + 1];

// ---------------- sort-by-k pipeline ----------------
__global__ void hist_kernel(const int* __restrict__ idx_k, int nnz) {
    int t = blockIdx.x * blockDim.x + threadIdx.x;
    if (t < nnz) atomicAdd(&g_hist[idx_k[t]], 1);
}

__global__ void scan_kernel() {
    if (threadIdx.x == 0) {
        int s = 0;
        for (int k = 0; k < ALG; ++k) {
            g_seg[k]    = s;
            g_cursor[k] = s;
            s += g_hist[k];
        }
        g_seg[ALG] = s;
    }
}

__global__ void scatter_kernel(const int* __restrict__ idx_i,
                               const int* __restrict__ idx_j,
                               const int* __restrict__ idx_k,
                               const float* __restrict__ coeff,
                               const float* __restrict__ alpha,
                               int nnz) {
    int t = blockIdx.x * blockDim.x + threadIdx.x;
    if (t >= nnz) return;
    int k   = idx_k[t];
    int pos = atomicAdd(&g_cursor[k], 1);
    unsigned pi = (unsigned)(idx_i[t] * PAD);       // pre-scaled smem row offset
    unsigned pj = (unsigned)(idx_j[t] * PAD);
    g_sorted[pos] = make_uint2(pi | (pj << 16), __float_as_uint(coeff[t] * alpha[0]));
}

// ---------------- main bilinear kernel ----------------
extern __shared__ float smem[];

__global__ __launch_bounds__(256, 2)
void bracket_kernel(const float* __restrict__ x, const float* __restrict__ y,
                    float* __restrict__ out, int batch) {
    float* xs = smem;                       // [ALG][PAD]
    float* ys = xs + ALG * PAD;             // [ALG][PAD]
    float* os = ys + ALG * PAD;             // [ALG][PAD]
    __shared__ int segs[ALG + 1];

    const int tid  = threadIdx.x;
    const int warp = tid >> 5;
    const int lane = tid & 31;
    const int b0   = blockIdx.x * TB;

    for (int k = tid; k <= ALG; k += blockDim.x) segs[k] = g_seg[k];

    // Stage x,y tile transposed: coalesced global reads, conflict-free smem writes.
    for (int b = warp; b < TB; b += NWARP) {
        const int gb = b0 + b;
        const bool ok = gb < batch;
        const float* xr = x + (size_t)gb * ALG;
        const float* yr = y + (size_t)gb * ALG;
        for (int d = lane; d < ALG; d += 32) {
            xs[d * PAD + b] = ok ? xr[d] : 0.f;
            ys[d * PAD + b] = ok ? yr[d] : 0.f;
        }
    }
    __syncthreads();

    // Each warp owns 31 k-values exclusively -> register accumulation, no atomics.
    const float* xl = xs + lane;            // lane == batch-within-tile
    const float* yl = ys + lane;
    const int k0 = warp * KPW;

    for (int k = k0; k < k0 + KPW; ++k) {
        int t = segs[k];
        const int e = segs[k + 1];
        float acc0 = 0.f, acc1 = 0.f;

        if ((t & 1) && t < e) {             // align to 16B for uint4 loads
            uint2 q = __ldg(&g_sorted[t]);
            acc0 = fmaf(__uint_as_float(q.y) * xl[q.x & 0xFFFFu], yl[q.x >> 16], acc0);
            ++t;
        }
        for (; t + 2 <= e; t += 2) {        // 2 triples per LDG.128
            uint4 q = __ldg((const uint4*)(g_sorted + t));
            acc0 = fmaf(__uint_as_float(q.y) * xl[q.x & 0xFFFFu], yl[q.x >> 16], acc0);
            acc1 = fmaf(__uint_as_float(q.w) * xl[q.z & 0xFFFFu], yl[q.z >> 16], acc1);
        }
        if (t < e) {
            uint2 q = __ldg(&g_sorted[t]);
            acc0 = fmaf(__uint_as_float(q.y) * xl[q.x & 0xFFFFu], yl[q.x >> 16], acc0);
        }
        os[k * PAD + lane] = acc0 + acc1;
    }
    __syncthreads();

    // Coalesced write-out (alpha already folded into coeff).
    for (int b = warp; b < TB; b += NWARP) {
        const int gb = b0 + b;
        if (gb >= batch) continue;
        float* orow = out + (size_t)gb * ALG;
        for (int d = lane; d < ALG; d += 32) orow[d] = os[d * PAD + b];
    }
}

// ---------------- launch ----------------
extern "C" void kernel_launch(void* const* d_in, const int* in_sizes, int n_in,
                              void* d_out, int out_size) {
    const float* x     = (const float*)d_in[0];
    const float* y     = (const float*)d_in[1];
    const int*   idx_i = (const int*)  d_in[2];
    const int*   idx_j = (const int*)  d_in[3];
    const int*   idx_k = (const int*)  d_in[4];
    const float* coeff = (const float*)d_in[5];
    const float* alpha = (const float*)d_in[6];

    int nnz = in_sizes[5];
    if (nnz > MAXNNZ) nnz = MAXNNZ;
    const int batch = in_sizes[0] / ALG;

    void* hist_ptr = nullptr;
    cudaGetSymbolAddress(&hist_ptr, g_hist);
    cudaMemsetAsync(hist_ptr, 0, ALG * sizeof(int));

    const int nb = (nnz + 255) / 256;
    hist_kernel   <<<nb, 256>>>(idx_k, nnz);
    scan_kernel   <<<1, 32>>>();
    scatter_kernel<<<nb, 256>>>(idx_i, idx_j, idx_k, coeff, alpha, nnz);

    const int smem_bytes = 3 * ALG * PAD * (int)sizeof(float);   // 98208 B
    cudaFuncSetAttribute(bracket_kernel,
                         cudaFuncAttributeMaxDynamicSharedMemorySize, smem_bytes);

    const int grid = (batch + TB - 1) / TB;                      // 256 CTAs
    bracket_kernel<<<grid, 256, smem_bytes>>>(x, y, (float*)d_out, batch);
}